// round 3
// baseline (speedup 1.0000x reference)
#include <cuda_runtime.h>

#define NN 100000

// ---------------- scratch (static device globals; no allocation) -------------
__device__ float    g_acc [NN * 64];  // GCN edge-sum -> GAT1 edge acc
__device__ float    g_h   [NN * 64];  // relu(GCN out) -> later h2 [N,32]
__device__ float    g_h1  [NN * 64];  // GAT1 h = in @ W1
__device__ float    g_acc2[NN * 32];  // GAT2 edge acc
__device__ float    g_deg [NN];
__device__ float    g_ssrc[NN];
__device__ float    g_sdst[NN];
__device__ unsigned g_menc[NN];
__device__ float2   g_pack[NN];       // {sdst, mf}
__device__ float    g_ecs [NN];
__device__ float    g_den [NN];

// ---------------- helpers ----------------------------------------------------
__device__ __forceinline__ unsigned fenc(float x) {
    unsigned u = __float_as_uint(x);
    return (u & 0x80000000u) ? ~u : (u | 0x80000000u);
}
__device__ __forceinline__ float fdec(unsigned k) {
    unsigned u = (k & 0x80000000u) ? (k & 0x7fffffffu) : ~k;
    return __uint_as_float(u);
}
__device__ __forceinline__ float lrelu(float z) { return z > 0.f ? z : 0.2f * z; }

__device__ __forceinline__ void red4(float* p, float4 v) {
    asm volatile("red.global.add.v4.f32 [%0], {%1, %2, %3, %4};"
                 :: "l"(p), "f"(v.x), "f"(v.y), "f"(v.z), "f"(v.w) : "memory");
}

// acc[0..31] += ink * w[0..31]  (w points at a 16B-aligned 32-float slice)
__device__ __forceinline__ void fma_row32(float ink, const float* w, float (&acc)[32]) {
    const float4* wr = (const float4*)w;
#pragma unroll
    for (int c4 = 0; c4 < 8; c4++) {
        float4 wv = wr[c4];
        acc[c4*4+0] = fmaf(ink, wv.x, acc[c4*4+0]);
        acc[c4*4+1] = fmaf(ink, wv.y, acc[c4*4+1]);
        acc[c4*4+2] = fmaf(ink, wv.z, acc[c4*4+2]);
        acc[c4*4+3] = fmaf(ink, wv.w, acc[c4*4+3]);
    }
}

// ---------------- kernels ----------------------------------------------------

// zero g_acc and g_deg (edges-only accumulation; self terms added in consumers)
__global__ void k_zero(int n) {
    int idx = blockIdx.x * blockDim.x + threadIdx.x;
    if (idx < n * 16) ((float4*)g_acc)[idx] = make_float4(0.f, 0.f, 0.f, 0.f);
    if (idx < n) g_deg[idx] = 0.f;
}

// clusterGCN edge pass: acc[dst] += x[src]; deg[dst] += 1
__global__ void k_edge0(const int* __restrict__ src, const int* __restrict__ dst,
                        const float4* __restrict__ x4, int e) {
    int t = blockIdx.x * blockDim.x + threadIdx.x;
    int warp = t >> 5, lane = t & 31;
    int sub = lane >> 4, q = lane & 15;
    int ed = warp * 2 + sub;
    if (ed >= e) return;
    int s = src[ed], d = dst[ed];
    float4 v = x4[(size_t)s * 16 + q];
    red4(g_acc + (size_t)d * 64 + q * 4, v);
    if (q == 0) atomicAdd(&g_deg[d], 1.0f);
}

// h = relu(((acc+x)/(deg+1)) @ W_out + x @ W_root + b_out); zero acc row after.
// 2 threads per node: warps 0-3 -> cols 0-31, warps 4-7 -> cols 32-63.
__global__ __launch_bounds__(256, 4) void k_gemm0(
        const float* __restrict__ x, const float* __restrict__ Wout,
        const float* __restrict__ bout, const float* __restrict__ Wroot, int n) {
    __shared__ float sWo[4096], sWr[4096], sb[64];
    int tid = threadIdx.x;
    for (int i = tid; i < 4096; i += 256) { sWo[i] = Wout[i]; sWr[i] = Wroot[i]; }
    if (tid < 64) sb[tid] = bout[tid];
    __syncthreads();
    int half = tid >> 7;
    int node = blockIdx.x * 128 + (tid & 127);
    if (node >= n) return;
    const float* wo = sWo + half * 32;
    const float* wr = sWr + half * 32;
    float acc[32];
#pragma unroll
    for (int c = 0; c < 32; c++) acc[c] = 0.f;
    float dinv = 1.0f / (g_deg[node] + 1.0f);
    const float4* ar = (const float4*)(g_acc + (size_t)node * 64);
    const float4* xr = (const float4*)(x + (size_t)node * 64);
#pragma unroll 1
    for (int k4 = 0; k4 < 16; k4++) {
        float4 av = ar[k4];
        float4 xv = xr[k4];
        float a0 = (av.x + xv.x) * dinv, a1 = (av.y + xv.y) * dinv;
        float a2 = (av.z + xv.z) * dinv, a3 = (av.w + xv.w) * dinv;
        fma_row32(a0, wo + (k4*4+0)*64, acc);
        fma_row32(a1, wo + (k4*4+1)*64, acc);
        fma_row32(a2, wo + (k4*4+2)*64, acc);
        fma_row32(a3, wo + (k4*4+3)*64, acc);
        fma_row32(xv.x, wr + (k4*4+0)*64, acc);
        fma_row32(xv.y, wr + (k4*4+1)*64, acc);
        fma_row32(xv.z, wr + (k4*4+2)*64, acc);
        fma_row32(xv.w, wr + (k4*4+3)*64, acc);
    }
    float4* hr = (float4*)(g_h + (size_t)node * 64 + half * 32);
    float4* zr = (float4*)(g_acc + (size_t)node * 64 + half * 32);
    const float* bb = sb + half * 32;
#pragma unroll
    for (int c4 = 0; c4 < 8; c4++) {
        float4 o;
        o.x = fmaxf(acc[c4*4+0] + bb[c4*4+0], 0.f);
        o.y = fmaxf(acc[c4*4+1] + bb[c4*4+1], 0.f);
        o.z = fmaxf(acc[c4*4+2] + bb[c4*4+2], 0.f);
        o.w = fmaxf(acc[c4*4+3] + bb[c4*4+3], 0.f);
        hr[c4] = o;
        zr[c4] = make_float4(0.f, 0.f, 0.f, 0.f);   // ready for GAT1 edge acc
    }
}

// GAT1: h1 = h @ W1; ssrc/sdst dots; seed menc with fenc(ssrc)
__global__ __launch_bounds__(256, 4) void k_gemm_gat1(
        const float* __restrict__ W, const float* __restrict__ asv,
        const float* __restrict__ adv, int n) {
    __shared__ float sW[4096], sas[64], sad[64], sred[512];
    int tid = threadIdx.x;
    for (int i = tid; i < 4096; i += 256) sW[i] = W[i];
    if (tid < 64) { sas[tid] = asv[tid]; sad[tid] = adv[tid]; }
    __syncthreads();
    int half = tid >> 7;
    int node = blockIdx.x * 128 + (tid & 127);
    bool act = node < n;
    const float* wp = sW + half * 32;
    float acc[32];
#pragma unroll
    for (int c = 0; c < 32; c++) acc[c] = 0.f;
    if (act) {
        const float4* hr = (const float4*)(g_h + (size_t)node * 64);
#pragma unroll 1
        for (int k4 = 0; k4 < 16; k4++) {
            float4 a = hr[k4];
            fma_row32(a.x, wp + (k4*4+0)*64, acc);
            fma_row32(a.y, wp + (k4*4+1)*64, acc);
            fma_row32(a.z, wp + (k4*4+2)*64, acc);
            fma_row32(a.w, wp + (k4*4+3)*64, acc);
        }
        float4* o = (float4*)(g_h1 + (size_t)node * 64 + half * 32);
#pragma unroll
        for (int c4 = 0; c4 < 8; c4++)
            o[c4] = make_float4(acc[c4*4+0], acc[c4*4+1], acc[c4*4+2], acc[c4*4+3]);
    }
    float ss = 0.f, sd = 0.f;
    const float* pas = sas + half * 32;
    const float* pad = sad + half * 32;
#pragma unroll
    for (int c = 0; c < 32; c++) { ss = fmaf(acc[c], pas[c], ss); sd = fmaf(acc[c], pad[c], sd); }
    sred[tid] = ss;
    sred[256 + tid] = sd;
    __syncthreads();
    if (tid < 128) {
        int nd = blockIdx.x * 128 + tid;
        if (nd < n) {
            float S = sred[tid] + sred[tid + 128];
            float D = sred[256 + tid] + sred[256 + tid + 128];
            g_ssrc[nd] = S;
            g_sdst[nd] = D;
            g_menc[nd] = fenc(S);   // self in the ssrc-max
        }
    }
}

// segment max of ssrc over in-neighbors (lrelu is monotone, sdst[d] constant per segment)
__global__ void k_edge_max(const int* __restrict__ src, const int* __restrict__ dst, int e) {
    int t = blockIdx.x * blockDim.x + threadIdx.x;
    if (t >= e) return;
    int s = src[t], d = dst[t];
    atomicMax(&g_menc[d], fenc(g_ssrc[s]));
}

// per-node: mf = lrelu(maxssrc + sdst); seed den with self exp; pack for edge pass
__global__ void k_prep(int n) {
    int i = blockIdx.x * blockDim.x + threadIdx.x;
    if (i >= n) return;
    float m  = fdec(g_menc[i]);
    float sdp = g_sdst[i];
    float mf = lrelu(m + sdp);
    float ecs = __expf(lrelu(g_ssrc[i] + sdp) - mf);
    g_pack[i] = make_float2(sdp, mf);
    g_den[i]  = ecs;
    g_ecs[i]  = ecs;
}

// unnormalized softmax aggregation: acc[dst] += e*h[src]; den[dst] += e
template<int C>
__global__ void k_edge_agg(const int* __restrict__ src, const int* __restrict__ dst, int e) {
    constexpr int L = C / 4, EPW = 32 / L;
    int t = blockIdx.x * blockDim.x + threadIdx.x;
    int warp = t >> 5, lane = t & 31;
    int sub = lane / L, q = lane % L;
    int ed = warp * EPW + sub;
    if (ed >= e) return;
    int s = src[ed], d = dst[ed];
    float2 p = g_pack[d];
    float ec = __expf(lrelu(g_ssrc[s] + p.x) - p.y);
    const float4* hb = (C == 64) ? (const float4*)g_h1 : (const float4*)g_h;
    float4 v = hb[(size_t)s * L + q];
    v.x *= ec; v.y *= ec; v.z *= ec; v.w *= ec;
    float* ab = (C == 64) ? g_acc : g_acc2;
    red4(ab + (size_t)d * C + q * 4, v);
    if (q == 0) atomicAdd(&g_den[d], ec);
}

// GAT2: in = relu((acc1 + ecs*h1)/den1 + b1); h2 = in @ W2; dots; menc seed;
// zero acc2 row.
__global__ __launch_bounds__(256, 4) void k_gemm_gat2(
        const float* __restrict__ W, const float* __restrict__ asv,
        const float* __restrict__ adv, const float* __restrict__ b1, int n) {
    __shared__ float sW[2048], sas[32], sad[32], sb1[64];
    int tid = threadIdx.x;
    for (int i = tid; i < 2048; i += 256) sW[i] = W[i];
    if (tid < 32) { sas[tid] = asv[tid]; sad[tid] = adv[tid]; }
    if (tid < 64) sb1[tid] = b1[tid];
    __syncthreads();
    int node = blockIdx.x * 256 + tid;
    if (node >= n) return;
    float acc[32];
#pragma unroll
    for (int c = 0; c < 32; c++) acc[c] = 0.f;
    float rd  = 1.0f / g_den[node];
    float ecs = g_ecs[node];
    const float4* ar = (const float4*)(g_acc + (size_t)node * 64);
    const float4* hr = (const float4*)(g_h1 + (size_t)node * 64);
#pragma unroll 1
    for (int k4 = 0; k4 < 16; k4++) {
        float4 a = ar[k4];
        float4 h = hr[k4];
        float i0 = fmaxf(fmaf(fmaf(ecs, h.x, a.x), rd, sb1[k4*4+0]), 0.f);
        float i1 = fmaxf(fmaf(fmaf(ecs, h.y, a.y), rd, sb1[k4*4+1]), 0.f);
        float i2 = fmaxf(fmaf(fmaf(ecs, h.z, a.z), rd, sb1[k4*4+2]), 0.f);
        float i3 = fmaxf(fmaf(fmaf(ecs, h.w, a.w), rd, sb1[k4*4+3]), 0.f);
        fma_row32(i0, sW + (k4*4+0)*32, acc);
        fma_row32(i1, sW + (k4*4+1)*32, acc);
        fma_row32(i2, sW + (k4*4+2)*32, acc);
        fma_row32(i3, sW + (k4*4+3)*32, acc);
    }
    float ss = 0.f, sd = 0.f;
#pragma unroll
    for (int c = 0; c < 32; c++) { ss = fmaf(acc[c], sas[c], ss); sd = fmaf(acc[c], sad[c], sd); }
    float4* o = (float4*)(g_h + (size_t)node * 32);
    float4* z = (float4*)(g_acc2 + (size_t)node * 32);
#pragma unroll
    for (int c4 = 0; c4 < 8; c4++) {
        o[c4] = make_float4(acc[c4*4+0], acc[c4*4+1], acc[c4*4+2], acc[c4*4+3]);
        z[c4] = make_float4(0.f, 0.f, 0.f, 0.f);
    }
    g_ssrc[node] = ss;
    g_sdst[node] = sd;
    g_menc[node] = fenc(ss);
}

// out = (acc2 + ecs*h2)/den2 + b2
__global__ void k_final(float4* __restrict__ out4, const float* __restrict__ b2, int n) {
    int idx = blockIdx.x * blockDim.x + threadIdx.x;
    if (idx >= n * 8) return;
    int i = idx >> 3, q = idx & 7;
    float rd  = 1.0f / g_den[i];
    float ecs = g_ecs[i];
    float4 a = ((const float4*)g_acc2)[(size_t)i * 8 + q];
    float4 h = ((const float4*)g_h)[(size_t)i * 8 + q];
    float4 b = ((const float4*)b2)[q];
    out4[idx] = make_float4(fmaf(fmaf(ecs, h.x, a.x), rd, b.x),
                            fmaf(fmaf(ecs, h.y, a.y), rd, b.y),
                            fmaf(fmaf(ecs, h.z, a.z), rd, b.z),
                            fmaf(fmaf(ecs, h.w, a.w), rd, b.w));
}

// ---------------- launch ------------------------------------------------------
extern "C" void kernel_launch(void* const* d_in, const int* in_sizes, int n_in,
                              void* d_out, int out_size) {
    const float* x    = (const float*)d_in[0];
    const int*   ei   = (const int*)  d_in[1];
    const float* Wout = (const float*)d_in[2];
    const float* bout = (const float*)d_in[3];
    const float* Wroot= (const float*)d_in[4];
    const float* W1   = (const float*)d_in[5];
    const float* as1  = (const float*)d_in[6];
    const float* ad1  = (const float*)d_in[7];
    const float* b1   = (const float*)d_in[8];
    const float* W2   = (const float*)d_in[9];
    const float* as2  = (const float*)d_in[10];
    const float* ad2  = (const float*)d_in[11];
    const float* b2   = (const float*)d_in[12];

    int n = in_sizes[0] / 64;
    int e = in_sizes[1] / 2;
    const int* src = ei;
    const int* dst = ei + e;

    const int TB = 256;
    int nb_zero = (n * 16 + TB - 1) / TB;
    int nb_g128 = (n + 127) / 128;
    int nb_g256 = (n + 255) / 256;
    int nb_e1   = (e + TB - 1) / TB;
    int nb_e16  = (e + 15) / 16;
    int nb_e32  = (e + 31) / 32;
    int nb_n8   = (n * 8 + TB - 1) / TB;

    // Layer 0: ClusterGCN
    k_zero <<<nb_zero, TB>>>(n);
    k_edge0<<<nb_e16, TB>>>(src, dst, (const float4*)x, e);
    k_gemm0<<<nb_g128, 256>>>(x, Wout, bout, Wroot, n);

    // Layer 1: GAT(64->64)
    k_gemm_gat1<<<nb_g128, 256>>>(W1, as1, ad1, n);
    k_edge_max <<<nb_e1, TB>>>(src, dst, e);
    k_prep     <<<nb_g256, TB>>>(n);
    k_edge_agg<64><<<nb_e16, TB>>>(src, dst, e);

    // Layer 2: GAT(64->32)
    k_gemm_gat2<<<nb_g256, 256>>>(W2, as2, ad2, b1, n);
    k_edge_max <<<nb_e1, TB>>>(src, dst, e);
    k_prep     <<<nb_g256, TB>>>(n);
    k_edge_agg<32><<<nb_e32, TB>>>(src, dst, e);

    k_final<<<nb_n8, TB>>>((float4*)d_out, b2, n);
}

// round 9
// speedup vs baseline: 1.6498x; 1.6498x over previous
#include <cuda_runtime.h>

#define NN 100000
#define EE 1600000

// ---------------- scratch (static device globals) ----------------------------
__device__ float    g_acc[NN * 64];   // agg0 out -> gat1 agg out (t1)
__device__ float    g_h  [NN * 64];   // relu(GCN out)
__device__ float    g_h1 [NN * 64];   // GAT1 h = in @ W1
__device__ float    g_h2 [NN * 32];   // GAT2 h
__device__ float    g_ssrc[NN];
__device__ float    g_sdst[NN];
__device__ unsigned g_cnt[NN];        // in-degree (excl self)
__device__ unsigned g_off[NN];        // CSR offsets (exclusive scan of cnt)
__device__ int      g_cur[NN];        // scatter cursors
__device__ unsigned g_part[512];      // scan partials
__device__ int      g_csr[EE];        // src ids grouped by dst

// ---------------- helpers ----------------------------------------------------
__device__ __forceinline__ float lrelu(float z) { return z > 0.f ? z : 0.2f * z; }

// ---------------- CSR build ---------------------------------------------------
__global__ void k_zero_cnt(int n) {
    int i = blockIdx.x * blockDim.x + threadIdx.x;
    if (i < n) g_cnt[i] = 0u;
}
__global__ void k_hist(const int* __restrict__ dst, int e) {
    int t = blockIdx.x * blockDim.x + threadIdx.x;
    if (t < e) atomicAdd(&g_cnt[dst[t]], 1u);
}
__global__ void k_scanA(int n) {
    __shared__ unsigned s[256];
    int lt = threadIdx.x, i = blockIdx.x * 256 + lt;
    unsigned v = (i < n) ? g_cnt[i] : 0u;
    s[lt] = v; __syncthreads();
#pragma unroll
    for (int ofs = 1; ofs < 256; ofs <<= 1) {
        unsigned t = (lt >= ofs) ? s[lt - ofs] : 0u;
        __syncthreads();
        s[lt] += t;
        __syncthreads();
    }
    if (i < n) g_off[i] = s[lt] - v;
    if (lt == 255) g_part[blockIdx.x] = s[255];
}
__global__ void k_scanB(int nb) {
    __shared__ unsigned s[512];
    int lt = threadIdx.x;
    unsigned v = (lt < nb) ? g_part[lt] : 0u;
    s[lt] = v; __syncthreads();
#pragma unroll
    for (int ofs = 1; ofs < 512; ofs <<= 1) {
        unsigned t = (lt >= ofs) ? s[lt - ofs] : 0u;
        __syncthreads();
        s[lt] += t;
        __syncthreads();
    }
    if (lt < nb) g_part[lt] = s[lt] - v;
}
__global__ void k_scanC(int n) {
    int i = blockIdx.x * 256 + threadIdx.x;
    if (i < n) {
        unsigned o = g_off[i] + g_part[blockIdx.x];
        g_off[i] = o;
        g_cur[i] = (int)o;
    }
}
__global__ void k_scatter(const int* __restrict__ src, const int* __restrict__ dst, int e) {
    int t = blockIdx.x * blockDim.x + threadIdx.x;
    if (t >= e) return;
    int d = dst[t];
    int pos = atomicAdd(&g_cur[d], 1);
    g_csr[pos] = src[t];
}

// ---------------- GCN neighbor sum (CSR gather, 16 lanes/node) ---------------
__global__ void k_agg0(const float4* __restrict__ x4, int n) {
    int t = blockIdx.x * blockDim.x + threadIdx.x;
    int g = t >> 4, q = t & 15;
    if (g >= n) return;
    unsigned o = g_off[g], c = g_cnt[g];
    float4 a = make_float4(0.f, 0.f, 0.f, 0.f);
    int sn = 0;
    if (c) sn = __ldg(&g_csr[o]);
    for (unsigned j = 0; j < c; j++) {
        int s = sn;
        if (j + 1 < c) sn = __ldg(&g_csr[o + j + 1]);
        float4 v = x4[(size_t)s * 16 + q];
        a.x += v.x; a.y += v.y; a.z += v.z; a.w += v.w;
    }
    ((float4*)g_acc)[(size_t)g * 16 + q] = a;
}

// ---------------- tiled GEMM core (plain scalar FFMA, no asm) -----------------
// sA: row-major [128][68]; sW: [64][NC] k-major (row = k, NC floats).
// Thread owns 8 rows x 2 adjacent cols (cols 2*ci, 2*ci+1). acc[16] plain float.
// NC2 = NC/2 (# of float2 col-pairs per k-row).
template<int NC2>
__device__ __forceinline__ void gemm_core(const float* __restrict__ sA,
                                          const float* __restrict__ sW,
                                          float (&acc)[16], int ri, int ci) {
    const float* a0 = sA + ri * 8 * 68;
#pragma unroll 2
    for (int k4 = 0; k4 < 16; k4++) {
        float2 w0 = ((const float2*)sW)[(k4 * 4 + 0) * NC2 + ci];
        float2 w1 = ((const float2*)sW)[(k4 * 4 + 1) * NC2 + ci];
        float2 w2 = ((const float2*)sW)[(k4 * 4 + 2) * NC2 + ci];
        float2 w3 = ((const float2*)sW)[(k4 * 4 + 3) * NC2 + ci];
#pragma unroll
        for (int j = 0; j < 8; j++) {
            float4 a = *(const float4*)&a0[j * 68 + k4 * 4];
            float e = acc[2 * j], o = acc[2 * j + 1];
            e = fmaf(a.x, w0.x, e); o = fmaf(a.x, w0.y, o);
            e = fmaf(a.y, w1.x, e); o = fmaf(a.y, w1.y, o);
            e = fmaf(a.z, w2.x, e); o = fmaf(a.z, w2.y, o);
            e = fmaf(a.w, w3.x, e); o = fmaf(a.w, w3.y, o);
            acc[2 * j] = e; acc[2 * j + 1] = o;
        }
    }
}

// GCN: h = relu(((acc+x)*dinv)@Wout + x@Wroot + bout). 512 thr, 128-row tile.
__global__ __launch_bounds__(512) void k_gemm0(
        const float4* __restrict__ x4, const float* __restrict__ Wout,
        const float* __restrict__ bout, const float* __restrict__ Wroot, int n) {
    extern __shared__ float smem[];
    float* sA = smem;                 // 128*68
    float* sW = smem + 128 * 68;      // 2*4096
    int tid = threadIdx.x;
    for (int i = tid; i < 4096; i += 512) { sW[i] = Wout[i]; sW[4096 + i] = Wroot[i]; }
    int rbase = blockIdx.x * 128;
    // panel 0: (acc + x) * dinv
#pragma unroll
    for (int it = 0; it < 4; it++) {
        int idx = it * 512 + tid, row = idx >> 4, k4 = idx & 15;
        int gr = rbase + row;
        float4 v = make_float4(0.f, 0.f, 0.f, 0.f);
        if (gr < n) {
            float4 a = ((const float4*)g_acc)[(size_t)gr * 16 + k4];
            float4 xv = x4[(size_t)gr * 16 + k4];
            float di = 1.f / ((float)g_cnt[gr] + 1.f);
            v = make_float4((a.x + xv.x) * di, (a.y + xv.y) * di,
                            (a.z + xv.z) * di, (a.w + xv.w) * di);
        }
        *(float4*)&sA[row * 68 + k4 * 4] = v;
    }
    __syncthreads();
    int ci = tid & 31, ri = tid >> 5;          // ri in [0,16): rows ri*8..+7
    float acc[16];
#pragma unroll
    for (int i = 0; i < 16; i++) acc[i] = 0.f;
    gemm_core<32>(sA, sW, acc, ri, ci);
    __syncthreads();
    // panel 1: x
#pragma unroll
    for (int it = 0; it < 4; it++) {
        int idx = it * 512 + tid, row = idx >> 4, k4 = idx & 15;
        int gr = rbase + row;
        float4 v = make_float4(0.f, 0.f, 0.f, 0.f);
        if (gr < n) v = x4[(size_t)gr * 16 + k4];
        *(float4*)&sA[row * 68 + k4 * 4] = v;
    }
    __syncthreads();
    gemm_core<32>(sA, sW + 4096, acc, ri, ci);
    float2 bv = __ldg((const float2*)bout + ci);
#pragma unroll
    for (int j = 0; j < 8; j++) {
        int gr = rbase + ri * 8 + j;
        if (gr < n) {
            float2 o = make_float2(fmaxf(acc[2 * j] + bv.x, 0.f),
                                   fmaxf(acc[2 * j + 1] + bv.y, 0.f));
            ((float2*)g_h)[(size_t)gr * 32 + ci] = o;
        }
    }
}

// GAT1: h1 = g_h @ W1 (raw). 512 thr.
__global__ __launch_bounds__(512) void k_gemm1(const float* __restrict__ W1, int n) {
    extern __shared__ float smem[];
    float* sA = smem;
    float* sW = smem + 128 * 68;
    int tid = threadIdx.x;
    for (int i = tid; i < 4096; i += 512) sW[i] = W1[i];
    int rbase = blockIdx.x * 128;
#pragma unroll
    for (int it = 0; it < 4; it++) {
        int idx = it * 512 + tid, row = idx >> 4, k4 = idx & 15;
        int gr = rbase + row;
        float4 v = make_float4(0.f, 0.f, 0.f, 0.f);
        if (gr < n) v = ((const float4*)g_h)[(size_t)gr * 16 + k4];
        *(float4*)&sA[row * 68 + k4 * 4] = v;
    }
    __syncthreads();
    int ci = tid & 31, ri = tid >> 5;
    float acc[16];
#pragma unroll
    for (int i = 0; i < 16; i++) acc[i] = 0.f;
    gemm_core<32>(sA, sW, acc, ri, ci);
#pragma unroll
    for (int j = 0; j < 8; j++) {
        int gr = rbase + ri * 8 + j;
        if (gr < n) {
            ((float2*)g_h1)[(size_t)gr * 32 + ci] =
                make_float2(acc[2 * j], acc[2 * j + 1]);
        }
    }
}

// GAT2: h2 = relu(t1 + b1) @ W2   (t1 = g_acc, NC=32). 256 thr.
__global__ __launch_bounds__(256) void k_gemm2(
        const float* __restrict__ W2, const float* __restrict__ b1, int n) {
    extern __shared__ float smem[];
    float* sA = smem;
    float* sW = smem + 128 * 68;      // 2048
    int tid = threadIdx.x;
    for (int i = tid; i < 2048; i += 256) sW[i] = W2[i];
    int rbase = blockIdx.x * 128;
#pragma unroll
    for (int it = 0; it < 8; it++) {
        int idx = it * 256 + tid, row = idx >> 4, k4 = idx & 15;
        int gr = rbase + row;
        float4 v = make_float4(0.f, 0.f, 0.f, 0.f);
        if (gr < n) {
            float4 a = ((const float4*)g_acc)[(size_t)gr * 16 + k4];
            float4 b = __ldg((const float4*)b1 + k4);
            v = make_float4(fmaxf(a.x + b.x, 0.f), fmaxf(a.y + b.y, 0.f),
                            fmaxf(a.z + b.z, 0.f), fmaxf(a.w + b.w, 0.f));
        }
        *(float4*)&sA[row * 68 + k4 * 4] = v;
    }
    __syncthreads();
    int ci = tid & 15, ri = tid >> 4;          // 16 col-pairs = 32 cols
    float acc[16];
#pragma unroll
    for (int i = 0; i < 16; i++) acc[i] = 0.f;
    gemm_core<16>(sA, sW, acc, ri, ci);
#pragma unroll
    for (int j = 0; j < 8; j++) {
        int gr = rbase + ri * 8 + j;
        if (gr < n) {
            ((float2*)g_h2)[(size_t)gr * 16 + ci] =
                make_float2(acc[2 * j], acc[2 * j + 1]);
        }
    }
}

// ---------------- attention dots (input global selected in device code) -------
template<int C>
__global__ void k_dots(const float* __restrict__ a_s,
                       const float* __restrict__ a_d, int n) {
    const int L = C / 4;
    const float* h = (C == 64) ? g_h1 : g_h2;   // device-side symbol access only
    int t = blockIdx.x * blockDim.x + threadIdx.x;
    int g = t / L, q = t % L;
    if (g >= n) return;
    float4 hv = ((const float4*)h)[(size_t)g * L + q];
    float4 as = __ldg((const float4*)a_s + q);
    float4 ad = __ldg((const float4*)a_d + q);
    float ss = hv.x * as.x + hv.y * as.y + hv.z * as.z + hv.w * as.w;
    float sd = hv.x * ad.x + hv.y * ad.y + hv.z * ad.z + hv.w * ad.w;
#pragma unroll
    for (int o = L / 2; o; o >>= 1) {
        ss += __shfl_xor_sync(0xFFFFFFFFu, ss, o);
        sd += __shfl_xor_sync(0xFFFFFFFFu, sd, o);
    }
    if (q == 0) { g_ssrc[g] = ss; g_sdst[g] = sd; }
}

// ---------------- GAT aggregation: online softmax over CSR -------------------
// Input h and non-final output selected via device-side symbols; only the
// final layer writes through the harness-owned out pointer.
template<int L, bool FINAL>
__global__ void k_gat_agg(float4* __restrict__ out_arg,
                          const float4* __restrict__ bias, int n) {
    const float4* h4 = (L == 16) ? (const float4*)g_h1 : (const float4*)g_h2;
    float4* out4 = FINAL ? out_arg : (float4*)g_acc;
    int t = blockIdx.x * blockDim.x + threadIdx.x;
    int g = t / L, q = t % L;
    if (g >= n) return;
    unsigned o = g_off[g], c = g_cnt[g];
    float sdp = g_sdst[g];
    float m = lrelu(g_ssrc[g] + sdp);           // self-loop logit
    float4 acc = h4[(size_t)g * L + q];          // self contribution (weight 1)
    float den = 1.f;
    int sn = 0; float ssn = 0.f;
    if (c) { sn = __ldg(&g_csr[o]); ssn = g_ssrc[sn]; }
    for (unsigned j = 0; j < c; j++) {
        int s = sn; float ss = ssn;
        float4 v = h4[(size_t)s * L + q];
        if (j + 1 < c) { sn = __ldg(&g_csr[o + j + 1]); ssn = g_ssrc[sn]; }
        float l = lrelu(ss + sdp);
        float w;
        if (l > m) {
            float r = __expf(m - l);
            acc.x *= r; acc.y *= r; acc.z *= r; acc.w *= r;
            den *= r; m = l; w = 1.f;
        } else {
            w = __expf(l - m);
        }
        acc.x = fmaf(w, v.x, acc.x); acc.y = fmaf(w, v.y, acc.y);
        acc.z = fmaf(w, v.z, acc.z); acc.w = fmaf(w, v.w, acc.w);
        den += w;
    }
    float rd = 1.f / den;
    float4 r4 = make_float4(acc.x * rd, acc.y * rd, acc.z * rd, acc.w * rd);
    if (FINAL) {
        float4 b = __ldg(bias + q);
        r4.x += b.x; r4.y += b.y; r4.z += b.z; r4.w += b.w;
    }
    out4[(size_t)g * L + q] = r4;
}

// ---------------- launch ------------------------------------------------------
extern "C" void kernel_launch(void* const* d_in, const int* in_sizes, int n_in,
                              void* d_out, int out_size) {
    const float* x    = (const float*)d_in[0];
    const int*   ei   = (const int*)  d_in[1];
    const float* Wout = (const float*)d_in[2];
    const float* bout = (const float*)d_in[3];
    const float* Wroot= (const float*)d_in[4];
    const float* W1   = (const float*)d_in[5];
    const float* as1  = (const float*)d_in[6];
    const float* ad1  = (const float*)d_in[7];
    const float* b1   = (const float*)d_in[8];
    const float* W2   = (const float*)d_in[9];
    const float* as2  = (const float*)d_in[10];
    const float* ad2  = (const float*)d_in[11];
    const float* b2   = (const float*)d_in[12];

    int n = in_sizes[0] / 64;
    int e = in_sizes[1] / 2;
    const int* src = ei;
    const int* dst = ei + e;

    // Deterministic, idempotent, capture-safe: opt in to >48KB dynamic smem.
    cudaFuncSetAttribute(k_gemm0, cudaFuncAttributeMaxDynamicSharedMemorySize, 128*68*4 + 32768);
    cudaFuncSetAttribute(k_gemm1, cudaFuncAttributeMaxDynamicSharedMemorySize, 128*68*4 + 16384);

    const int TB = 256;
    int nbs   = (n + 255) / 256;
    int nb_e  = (e + TB - 1) / TB;
    int nb_g  = (n + 127) / 128;
    int nb_16 = (n * 16 + TB - 1) / TB;
    int nb_8  = (n * 8 + TB - 1) / TB;

    // CSR build
    k_zero_cnt<<<nbs, TB>>>(n);
    k_hist    <<<nb_e, TB>>>(dst, e);
    k_scanA   <<<nbs, 256>>>(n);
    k_scanB   <<<1, 512>>>(nbs);
    k_scanC   <<<nbs, 256>>>(n);
    k_scatter <<<nb_e, TB>>>(src, dst, e);

    // Layer 0: ClusterGCN
    k_agg0 <<<nb_16, TB>>>((const float4*)x, n);
    k_gemm0<<<nb_g, 512, 128*68*4 + 32768>>>((const float4*)x, Wout, bout, Wroot, n);

    // Layer 1: GAT(64->64)
    k_gemm1<<<nb_g, 512, 128*68*4 + 16384>>>(W1, n);
    k_dots<64><<<nb_16, TB>>>(as1, ad1, n);
    k_gat_agg<16, false><<<nb_16, TB>>>(nullptr, nullptr, n);

    // Layer 2: GAT(64->32)
    k_gemm2<<<nb_g, 256, 128*68*4 + 8192>>>(W2, b1, n);
    k_dots<32><<<nb_8, TB>>>(as2, ad2, n);
    k_gat_agg<8, true><<<nb_8, TB>>>((float4*)d_out, (const float4*)b2, n);
}

// round 10
// speedup vs baseline: 1.7310x; 1.0492x over previous
#include <cuda_runtime.h>

#define NN 100000
#define EE 1600000
typedef unsigned long long ull;

// ---------------- scratch (static device globals) ----------------------------
__device__ float    g_acc[NN * 64];   // agg0 out -> gat1 agg out (t1)
__device__ float    g_h  [NN * 64];   // relu(GCN out)
__device__ float    g_h1 [NN * 64];   // GAT1 h = in @ W1
__device__ float    g_h2 [NN * 32];   // GAT2 h
__device__ float    g_ssrc[NN];
__device__ float    g_sdst[NN];
__device__ unsigned g_cnt[NN];        // in-degree (excl self)
__device__ unsigned g_off[NN];        // CSR offsets (exclusive scan of cnt)
__device__ int      g_cur[NN];        // scatter cursors
__device__ unsigned g_part[512];      // scan partials
__device__ int      g_csr[EE];        // src ids grouped by dst

// ---------------- helpers ----------------------------------------------------
__device__ __forceinline__ float lrelu(float z) { return z > 0.f ? z : 0.2f * z; }

__device__ __forceinline__ ull pack2(float a) {
    ull r; asm("mov.b64 %0, {%1, %1};" : "=l"(r) : "f"(a)); return r;
}
__device__ __forceinline__ void ffma2(ull& d, ull a, ull b) {
    asm("fma.rn.f32x2 %0, %1, %2, %0;" : "+l"(d) : "l"(a), "l"(b));
}
__device__ __forceinline__ float2 upk(ull v) {
    float2 f; asm("mov.b64 {%0, %1}, %2;" : "=f"(f.x), "=f"(f.y) : "l"(v)); return f;
}

// ---------------- CSR build ---------------------------------------------------
__global__ void k_zero_cnt(int n) {
    int i = blockIdx.x * blockDim.x + threadIdx.x;
    if (i < n) g_cnt[i] = 0u;
}
__global__ void k_hist(const int* __restrict__ dst, int e) {
    int t = blockIdx.x * blockDim.x + threadIdx.x;
    if (t < e) atomicAdd(&g_cnt[dst[t]], 1u);
}
__global__ void k_scanA(int n) {
    __shared__ unsigned s[256];
    int lt = threadIdx.x, i = blockIdx.x * 256 + lt;
    unsigned v = (i < n) ? g_cnt[i] : 0u;
    s[lt] = v; __syncthreads();
#pragma unroll
    for (int ofs = 1; ofs < 256; ofs <<= 1) {
        unsigned t = (lt >= ofs) ? s[lt - ofs] : 0u;
        __syncthreads();
        s[lt] += t;
        __syncthreads();
    }
    if (i < n) g_off[i] = s[lt] - v;
    if (lt == 255) g_part[blockIdx.x] = s[255];
}
__global__ void k_scanB(int nb) {
    __shared__ unsigned s[512];
    int lt = threadIdx.x;
    unsigned v = (lt < nb) ? g_part[lt] : 0u;
    s[lt] = v; __syncthreads();
#pragma unroll
    for (int ofs = 1; ofs < 512; ofs <<= 1) {
        unsigned t = (lt >= ofs) ? s[lt - ofs] : 0u;
        __syncthreads();
        s[lt] += t;
        __syncthreads();
    }
    if (lt < nb) g_part[lt] = s[lt] - v;
}
__global__ void k_scanC(int n) {
    int i = blockIdx.x * 256 + threadIdx.x;
    if (i < n) {
        unsigned o = g_off[i] + g_part[blockIdx.x];
        g_off[i] = o;
        g_cur[i] = (int)o;
    }
}
__global__ void k_scatter(const int* __restrict__ src, const int* __restrict__ dst, int e) {
    int t = blockIdx.x * blockDim.x + threadIdx.x;
    if (t >= e) return;
    int d = dst[t];
    int pos = atomicAdd(&g_cur[d], 1);
    g_csr[pos] = src[t];
}

// ---------------- GCN neighbor sum (CSR gather, 16 lanes/node) ---------------
__global__ void k_agg0(const float4* __restrict__ x4, int n) {
    int t = blockIdx.x * blockDim.x + threadIdx.x;
    int g = t >> 4, q = t & 15;
    if (g >= n) return;
    unsigned o = g_off[g], c = g_cnt[g];
    float4 a = make_float4(0.f, 0.f, 0.f, 0.f);
    int sn = 0;
    if (c) sn = __ldg(&g_csr[o]);
    for (unsigned j = 0; j < c; j++) {
        int s = sn;
        if (j + 1 < c) sn = __ldg(&g_csr[o + j + 1]);
        float4 v = x4[(size_t)s * 16 + q];
        a.x += v.x; a.y += v.y; a.z += v.z; a.w += v.w;
    }
    ((float4*)g_acc)[(size_t)g * 16 + q] = a;
}

// ---------------- tiled GEMM core (packed f32x2 FFMA) -------------------------
// sA: row-major [128][68]; sW: [64][NC] k-major. Thread owns 8 rows x 2 cols
// (cols 2*ci, 2*ci+1). NC2 = NC/2 col-pairs per k-row. acc[8] packed f32x2.
template<int NC2>
__device__ __forceinline__ void gemm_core2(const float* __restrict__ sA,
                                           const float* __restrict__ sW,
                                           ull* acc, int ri, int ci) {
    const float* a0 = sA + ri * 8 * 68;
#pragma unroll 2
    for (int k = 0; k < 64; k++) {
        ull w = ((const ull*)sW)[k * NC2 + ci];
#pragma unroll
        for (int j = 0; j < 8; j++) {
            ull av = pack2(a0[j * 68 + k]);
            ffma2(acc[j], av, w);
        }
    }
}

// GCN: h = relu(((acc+x)*dinv)@Wout + x@Wroot + bout). 512 thr, 128-row tile.
__global__ __launch_bounds__(512) void k_gemm0(
        const float4* __restrict__ x4, const float* __restrict__ Wout,
        const float* __restrict__ bout, const float* __restrict__ Wroot, int n) {
    extern __shared__ float smem[];
    float* sA = smem;                 // 128*68
    float* sW = smem + 128 * 68;      // 2*4096
    int tid = threadIdx.x;
    for (int i = tid; i < 4096; i += 512) { sW[i] = Wout[i]; sW[4096 + i] = Wroot[i]; }
    int rbase = blockIdx.x * 128;
    // panel 0: (acc + x) * dinv
#pragma unroll
    for (int it = 0; it < 4; it++) {
        int idx = it * 512 + tid, row = idx >> 4, k4 = idx & 15;
        int gr = rbase + row;
        float4 v = make_float4(0.f, 0.f, 0.f, 0.f);
        if (gr < n) {
            float4 a = ((const float4*)g_acc)[(size_t)gr * 16 + k4];
            float4 xv = x4[(size_t)gr * 16 + k4];
            float di = 1.f / ((float)g_cnt[gr] + 1.f);
            v = make_float4((a.x + xv.x) * di, (a.y + xv.y) * di,
                            (a.z + xv.z) * di, (a.w + xv.w) * di);
        }
        *(float4*)&sA[row * 68 + k4 * 4] = v;
    }
    __syncthreads();
    int ci = tid & 31, ri = tid >> 5;          // warp ri: rows ri*8..+7
    ull acc[8];
#pragma unroll
    for (int i = 0; i < 8; i++) acc[i] = 0ull;
    gemm_core2<32>(sA, sW, acc, ri, ci);
    __syncthreads();
    // panel 1: x
#pragma unroll
    for (int it = 0; it < 4; it++) {
        int idx = it * 512 + tid, row = idx >> 4, k4 = idx & 15;
        int gr = rbase + row;
        float4 v = make_float4(0.f, 0.f, 0.f, 0.f);
        if (gr < n) v = x4[(size_t)gr * 16 + k4];
        *(float4*)&sA[row * 68 + k4 * 4] = v;
    }
    __syncthreads();
    gemm_core2<32>(sA, sW + 4096, acc, ri, ci);
    float2 bv = __ldg((const float2*)bout + ci);
#pragma unroll
    for (int j = 0; j < 8; j++) {
        int gr = rbase + ri * 8 + j;
        if (gr < n) {
            float2 p = upk(acc[j]);
            float2 o = make_float2(fmaxf(p.x + bv.x, 0.f), fmaxf(p.y + bv.y, 0.f));
            ((float2*)g_h)[(size_t)gr * 32 + ci] = o;
        }
    }
}

// GAT1: h1 = g_h @ W1; fused attention dots (warp-reduce). 512 thr.
__global__ __launch_bounds__(512) void k_gemm1(
        const float* __restrict__ W1, const float* __restrict__ as1,
        const float* __restrict__ ad1, int n) {
    extern __shared__ float smem[];
    float* sA = smem;
    float* sW = smem + 128 * 68;
    int tid = threadIdx.x;
    for (int i = tid; i < 4096; i += 512) sW[i] = W1[i];
    int rbase = blockIdx.x * 128;
#pragma unroll
    for (int it = 0; it < 4; it++) {
        int idx = it * 512 + tid, row = idx >> 4, k4 = idx & 15;
        int gr = rbase + row;
        float4 v = make_float4(0.f, 0.f, 0.f, 0.f);
        if (gr < n) v = ((const float4*)g_h)[(size_t)gr * 16 + k4];
        *(float4*)&sA[row * 68 + k4 * 4] = v;
    }
    __syncthreads();
    int ci = tid & 31, ri = tid >> 5;
    ull acc[8];
#pragma unroll
    for (int i = 0; i < 8; i++) acc[i] = 0ull;
    gemm_core2<32>(sA, sW, acc, ri, ci);
    float2 asv = __ldg((const float2*)as1 + ci);
    float2 adv = __ldg((const float2*)ad1 + ci);
#pragma unroll
    for (int j = 0; j < 8; j++) {
        int gr = rbase + ri * 8 + j;
        float2 p = upk(acc[j]);
        if (gr < n) ((float2*)g_h1)[(size_t)gr * 32 + ci] = p;
        float ps = p.x * asv.x + p.y * asv.y;
        float pd = p.x * adv.x + p.y * adv.y;
#pragma unroll
        for (int o = 16; o; o >>= 1) {
            ps += __shfl_xor_sync(0xFFFFFFFFu, ps, o);
            pd += __shfl_xor_sync(0xFFFFFFFFu, pd, o);
        }
        if (ci == 0 && gr < n) { g_ssrc[gr] = ps; g_sdst[gr] = pd; }
    }
}

// GAT2: h2 = relu(t1 + b1) @ W2; fused dots (half-warp reduce). 256 thr.
__global__ __launch_bounds__(256) void k_gemm2(
        const float* __restrict__ W2, const float* __restrict__ b1,
        const float* __restrict__ as2, const float* __restrict__ ad2, int n) {
    extern __shared__ float smem[];
    float* sA = smem;
    float* sW = smem + 128 * 68;      // 2048
    int tid = threadIdx.x;
    for (int i = tid; i < 2048; i += 256) sW[i] = W2[i];
    int rbase = blockIdx.x * 128;
#pragma unroll
    for (int it = 0; it < 8; it++) {
        int idx = it * 256 + tid, row = idx >> 4, k4 = idx & 15;
        int gr = rbase + row;
        float4 v = make_float4(0.f, 0.f, 0.f, 0.f);
        if (gr < n) {
            float4 a = ((const float4*)g_acc)[(size_t)gr * 16 + k4];
            float4 b = __ldg((const float4*)b1 + k4);
            v = make_float4(fmaxf(a.x + b.x, 0.f), fmaxf(a.y + b.y, 0.f),
                            fmaxf(a.z + b.z, 0.f), fmaxf(a.w + b.w, 0.f));
        }
        *(float4*)&sA[row * 68 + k4 * 4] = v;
    }
    __syncthreads();
    int ci = tid & 15, ri = tid >> 4;          // 16 col-pairs = 32 cols
    ull acc[8];
#pragma unroll
    for (int i = 0; i < 8; i++) acc[i] = 0ull;
    gemm_core2<16>(sA, sW, acc, ri, ci);
    float2 asv = __ldg((const float2*)as2 + ci);
    float2 adv = __ldg((const float2*)ad2 + ci);
#pragma unroll
    for (int j = 0; j < 8; j++) {
        int gr = rbase + ri * 8 + j;
        float2 p = upk(acc[j]);
        if (gr < n) ((float2*)g_h2)[(size_t)gr * 16 + ci] = p;
        float ps = p.x * asv.x + p.y * asv.y;
        float pd = p.x * adv.x + p.y * adv.y;
#pragma unroll
        for (int o = 8; o; o >>= 1) {          // xor<16 stays within each half-warp
            ps += __shfl_xor_sync(0xFFFFFFFFu, ps, o);
            pd += __shfl_xor_sync(0xFFFFFFFFu, pd, o);
        }
        if (ci == 0 && gr < n) { g_ssrc[gr] = ps; g_sdst[gr] = pd; }
    }
}

// ---------------- GAT aggregation: online softmax over CSR -------------------
// Input h and non-final output selected via device-side symbols; only the
// final layer writes through the harness-owned out pointer.
template<int L, bool FINAL>
__global__ void k_gat_agg(float4* __restrict__ out_arg,
                          const float4* __restrict__ bias, int n) {
    const float4* h4 = (L == 16) ? (const float4*)g_h1 : (const float4*)g_h2;
    float4* out4 = FINAL ? out_arg : (float4*)g_acc;
    int t = blockIdx.x * blockDim.x + threadIdx.x;
    int g = t / L, q = t % L;
    if (g >= n) return;
    unsigned o = g_off[g], c = g_cnt[g];
    float sdp = g_sdst[g];
    float m = lrelu(g_ssrc[g] + sdp);           // self-loop logit
    float4 acc = h4[(size_t)g * L + q];          // self contribution (weight 1)
    float den = 1.f;
    int sn = 0; float ssn = 0.f;
    if (c) { sn = __ldg(&g_csr[o]); ssn = g_ssrc[sn]; }
    for (unsigned j = 0; j < c; j++) {
        int s = sn; float ss = ssn;
        float4 v = h4[(size_t)s * L + q];
        if (j + 1 < c) { sn = __ldg(&g_csr[o + j + 1]); ssn = g_ssrc[sn]; }
        float l = lrelu(ss + sdp);
        float w;
        if (l > m) {
            float r = __expf(m - l);
            acc.x *= r; acc.y *= r; acc.z *= r; acc.w *= r;
            den *= r; m = l; w = 1.f;
        } else {
            w = __expf(l - m);
        }
        acc.x = fmaf(w, v.x, acc.x); acc.y = fmaf(w, v.y, acc.y);
        acc.z = fmaf(w, v.z, acc.z); acc.w = fmaf(w, v.w, acc.w);
        den += w;
    }
    float rd = 1.f / den;
    float4 r4 = make_float4(acc.x * rd, acc.y * rd, acc.z * rd, acc.w * rd);
    if (FINAL) {
        float4 b = __ldg(bias + q);
        r4.x += b.x; r4.y += b.y; r4.z += b.z; r4.w += b.w;
    }
    out4[(size_t)g * L + q] = r4;
}

// ---------------- launch ------------------------------------------------------
extern "C" void kernel_launch(void* const* d_in, const int* in_sizes, int n_in,
                              void* d_out, int out_size) {
    const float* x    = (const float*)d_in[0];
    const int*   ei   = (const int*)  d_in[1];
    const float* Wout = (const float*)d_in[2];
    const float* bout = (const float*)d_in[3];
    const float* Wroot= (const float*)d_in[4];
    const float* W1   = (const float*)d_in[5];
    const float* as1  = (const float*)d_in[6];
    const float* ad1  = (const float*)d_in[7];
    const float* b1   = (const float*)d_in[8];
    const float* W2   = (const float*)d_in[9];
    const float* as2  = (const float*)d_in[10];
    const float* ad2  = (const float*)d_in[11];
    const float* b2   = (const float*)d_in[12];

    int n = in_sizes[0] / 64;
    int e = in_sizes[1] / 2;
    const int* src = ei;
    const int* dst = ei + e;

    // Deterministic, idempotent, capture-safe: opt in to >48KB dynamic smem.
    cudaFuncSetAttribute(k_gemm0, cudaFuncAttributeMaxDynamicSharedMemorySize, 128*68*4 + 32768);
    cudaFuncSetAttribute(k_gemm1, cudaFuncAttributeMaxDynamicSharedMemorySize, 128*68*4 + 16384);

    const int TB = 256;
    int nbs   = (n + 255) / 256;
    int nb_e  = (e + TB - 1) / TB;
    int nb_g  = (n + 127) / 128;
    int nb_16 = (n * 16 + TB - 1) / TB;
    int nb_8  = (n * 8 + TB - 1) / TB;

    // CSR build
    k_zero_cnt<<<nbs, TB>>>(n);
    k_hist    <<<nb_e, TB>>>(dst, e);
    k_scanA   <<<nbs, 256>>>(n);
    k_scanB   <<<1, 512>>>(nbs);
    k_scanC   <<<nbs, 256>>>(n);
    k_scatter <<<nb_e, TB>>>(src, dst, e);

    // Layer 0: ClusterGCN
    k_agg0 <<<nb_16, TB>>>((const float4*)x, n);
    k_gemm0<<<nb_g, 512, 128*68*4 + 32768>>>((const float4*)x, Wout, bout, Wroot, n);

    // Layer 1: GAT(64->64)  (dots fused into gemm1 epilogue)
    k_gemm1<<<nb_g, 512, 128*68*4 + 16384>>>(W1, as1, ad1, n);
    k_gat_agg<16, false><<<nb_16, TB>>>(nullptr, nullptr, n);

    // Layer 2: GAT(64->32)  (dots fused into gemm2 epilogue)
    k_gemm2<<<nb_g, 256, 128*68*4 + 8192>>>(W2, b1, as2, ad2, n);
    k_gat_agg<8, true><<<nb_8, TB>>>((float4*)d_out, (const float4*)b2, n);
}

// round 11
// speedup vs baseline: 1.7929x; 1.0357x over previous
#include <cuda_runtime.h>

#define NN 100000
#define EE 1600000
typedef unsigned long long ull;

// ---------------- scratch (static device globals) ----------------------------
__device__ float    g_acc[NN * 64];   // agg0 out -> gat1 agg out (t1)
__device__ float    g_h  [NN * 64];   // relu(GCN out)
__device__ float    g_h1 [NN * 64];   // GAT1 h = in @ W1
__device__ float    g_h2 [NN * 32];   // GAT2 h
__device__ float    g_ssrc[NN];
__device__ float    g_sdst[NN];
__device__ unsigned g_cnt[NN];        // in-degree (excl self)
__device__ unsigned g_off[NN];        // CSR offsets (exclusive scan of cnt)
__device__ int      g_cur[NN];        // scatter cursors
__device__ unsigned g_part[512];      // scan partials
__device__ int      g_csr[EE];        // src ids grouped by dst

// ---------------- helpers ----------------------------------------------------
__device__ __forceinline__ float lrelu(float z) { return z > 0.f ? z : 0.2f * z; }

__device__ __forceinline__ ull pack2(float a) {
    ull r; asm("mov.b64 %0, {%1, %1};" : "=l"(r) : "f"(a)); return r;
}
__device__ __forceinline__ void ffma2(ull& d, ull a, ull b) {
    asm("fma.rn.f32x2 %0, %1, %2, %0;" : "+l"(d) : "l"(a), "l"(b));
}
__device__ __forceinline__ float2 upk(ull v) {
    float2 f; asm("mov.b64 {%0, %1}, %2;" : "=f"(f.x), "=f"(f.y) : "l"(v)); return f;
}

// ---------------- CSR build ---------------------------------------------------
__global__ void k_zero_cnt(int n) {
    int i = blockIdx.x * blockDim.x + threadIdx.x;
    if (i < n) g_cnt[i] = 0u;
}
__global__ void k_hist(const int* __restrict__ dst, int e) {
    int t = blockIdx.x * blockDim.x + threadIdx.x;
    if (t < e) atomicAdd(&g_cnt[dst[t]], 1u);
}
__global__ void k_scanA(int n) {
    __shared__ unsigned s[256];
    int lt = threadIdx.x, i = blockIdx.x * 256 + lt;
    unsigned v = (i < n) ? g_cnt[i] : 0u;
    s[lt] = v; __syncthreads();
#pragma unroll
    for (int ofs = 1; ofs < 256; ofs <<= 1) {
        unsigned t = (lt >= ofs) ? s[lt - ofs] : 0u;
        __syncthreads();
        s[lt] += t;
        __syncthreads();
    }
    if (i < n) g_off[i] = s[lt] - v;
    if (lt == 255) g_part[blockIdx.x] = s[255];
}
__global__ void k_scanB(int nb) {
    __shared__ unsigned s[512];
    int lt = threadIdx.x;
    unsigned v = (lt < nb) ? g_part[lt] : 0u;
    s[lt] = v; __syncthreads();
#pragma unroll
    for (int ofs = 1; ofs < 512; ofs <<= 1) {
        unsigned t = (lt >= ofs) ? s[lt - ofs] : 0u;
        __syncthreads();
        s[lt] += t;
        __syncthreads();
    }
    if (lt < nb) g_part[lt] = s[lt] - v;
}
__global__ void k_scanC(int n) {
    int i = blockIdx.x * 256 + threadIdx.x;
    if (i < n) {
        unsigned o = g_off[i] + g_part[blockIdx.x];
        g_off[i] = o;
        g_cur[i] = (int)o;
    }
}
__global__ void k_scatter(const int* __restrict__ src, const int* __restrict__ dst, int e) {
    int t = blockIdx.x * blockDim.x + threadIdx.x;
    if (t >= e) return;
    int d = dst[t];
    int pos = atomicAdd(&g_cur[d], 1);
    g_csr[pos] = src[t];
}

// ---------------- GCN neighbor sum (CSR gather, 16 lanes/node, unroll 2) ------
__global__ void k_agg0(const float4* __restrict__ x4, int n) {
    int t = blockIdx.x * blockDim.x + threadIdx.x;
    int g = t >> 4, q = t & 15;
    if (g >= n) return;
    unsigned o = g_off[g], c = g_cnt[g];
    float4 a = make_float4(0.f, 0.f, 0.f, 0.f);
    float4 b = make_float4(0.f, 0.f, 0.f, 0.f);
    unsigned j = 0;
    for (; j + 2 <= c; j += 2) {
        int s0 = __ldg(&g_csr[o + j]);
        int s1 = __ldg(&g_csr[o + j + 1]);
        float4 v0 = x4[(size_t)s0 * 16 + q];
        float4 v1 = x4[(size_t)s1 * 16 + q];
        a.x += v0.x; a.y += v0.y; a.z += v0.z; a.w += v0.w;
        b.x += v1.x; b.y += v1.y; b.z += v1.z; b.w += v1.w;
    }
    if (j < c) {
        int s0 = __ldg(&g_csr[o + j]);
        float4 v0 = x4[(size_t)s0 * 16 + q];
        a.x += v0.x; a.y += v0.y; a.z += v0.z; a.w += v0.w;
    }
    a.x += b.x; a.y += b.y; a.z += b.z; a.w += b.w;
    ((float4*)g_acc)[(size_t)g * 16 + q] = a;
}

// ---------------- tiled GEMM core (packed f32x2 FFMA) -------------------------
template<int NC2>
__device__ __forceinline__ void gemm_core2(const float* __restrict__ sA,
                                           const float* __restrict__ sW,
                                           ull* acc, int ri, int ci) {
    const float* a0 = sA + ri * 8 * 68;
#pragma unroll 2
    for (int k = 0; k < 64; k++) {
        ull w = ((const ull*)sW)[k * NC2 + ci];
#pragma unroll
        for (int j = 0; j < 8; j++) {
            ull av = pack2(a0[j * 68 + k]);
            ffma2(acc[j], av, w);
        }
    }
}

// GCN: h = relu(((acc+x)*dinv)@Wout + x@Wroot + bout). 512 thr, 128-row tile.
__global__ __launch_bounds__(512) void k_gemm0(
        const float4* __restrict__ x4, const float* __restrict__ Wout,
        const float* __restrict__ bout, const float* __restrict__ Wroot, int n) {
    extern __shared__ float smem[];
    float* sA = smem;                 // 128*68
    float* sW = smem + 128 * 68;      // 2*4096
    int tid = threadIdx.x;
    for (int i = tid; i < 4096; i += 512) { sW[i] = Wout[i]; sW[4096 + i] = Wroot[i]; }
    int rbase = blockIdx.x * 128;
#pragma unroll
    for (int it = 0; it < 4; it++) {
        int idx = it * 512 + tid, row = idx >> 4, k4 = idx & 15;
        int gr = rbase + row;
        float4 v = make_float4(0.f, 0.f, 0.f, 0.f);
        if (gr < n) {
            float4 a = ((const float4*)g_acc)[(size_t)gr * 16 + k4];
            float4 xv = x4[(size_t)gr * 16 + k4];
            float di = 1.f / ((float)g_cnt[gr] + 1.f);
            v = make_float4((a.x + xv.x) * di, (a.y + xv.y) * di,
                            (a.z + xv.z) * di, (a.w + xv.w) * di);
        }
        *(float4*)&sA[row * 68 + k4 * 4] = v;
    }
    __syncthreads();
    int ci = tid & 31, ri = tid >> 5;
    ull acc[8];
#pragma unroll
    for (int i = 0; i < 8; i++) acc[i] = 0ull;
    gemm_core2<32>(sA, sW, acc, ri, ci);
    __syncthreads();
#pragma unroll
    for (int it = 0; it < 4; it++) {
        int idx = it * 512 + tid, row = idx >> 4, k4 = idx & 15;
        int gr = rbase + row;
        float4 v = make_float4(0.f, 0.f, 0.f, 0.f);
        if (gr < n) v = x4[(size_t)gr * 16 + k4];
        *(float4*)&sA[row * 68 + k4 * 4] = v;
    }
    __syncthreads();
    gemm_core2<32>(sA, sW + 4096, acc, ri, ci);
    float2 bv = __ldg((const float2*)bout + ci);
#pragma unroll
    for (int j = 0; j < 8; j++) {
        int gr = rbase + ri * 8 + j;
        if (gr < n) {
            float2 p = upk(acc[j]);
            float2 o = make_float2(fmaxf(p.x + bv.x, 0.f), fmaxf(p.y + bv.y, 0.f));
            ((float2*)g_h)[(size_t)gr * 32 + ci] = o;
        }
    }
}

// GAT1: h1 = g_h @ W1; fused attention dots (warp-reduce). 512 thr.
__global__ __launch_bounds__(512) void k_gemm1(
        const float* __restrict__ W1, const float* __restrict__ as1,
        const float* __restrict__ ad1, int n) {
    extern __shared__ float smem[];
    float* sA = smem;
    float* sW = smem + 128 * 68;
    int tid = threadIdx.x;
    for (int i = tid; i < 4096; i += 512) sW[i] = W1[i];
    int rbase = blockIdx.x * 128;
#pragma unroll
    for (int it = 0; it < 4; it++) {
        int idx = it * 512 + tid, row = idx >> 4, k4 = idx & 15;
        int gr = rbase + row;
        float4 v = make_float4(0.f, 0.f, 0.f, 0.f);
        if (gr < n) v = ((const float4*)g_h)[(size_t)gr * 16 + k4];
        *(float4*)&sA[row * 68 + k4 * 4] = v;
    }
    __syncthreads();
    int ci = tid & 31, ri = tid >> 5;
    ull acc[8];
#pragma unroll
    for (int i = 0; i < 8; i++) acc[i] = 0ull;
    gemm_core2<32>(sA, sW, acc, ri, ci);
    float2 asv = __ldg((const float2*)as1 + ci);
    float2 adv = __ldg((const float2*)ad1 + ci);
#pragma unroll
    for (int j = 0; j < 8; j++) {
        int gr = rbase + ri * 8 + j;
        float2 p = upk(acc[j]);
        if (gr < n) ((float2*)g_h1)[(size_t)gr * 32 + ci] = p;
        float ps = p.x * asv.x + p.y * asv.y;
        float pd = p.x * adv.x + p.y * adv.y;
#pragma unroll
        for (int o = 16; o; o >>= 1) {
            ps += __shfl_xor_sync(0xFFFFFFFFu, ps, o);
            pd += __shfl_xor_sync(0xFFFFFFFFu, pd, o);
        }
        if (ci == 0 && gr < n) { g_ssrc[gr] = ps; g_sdst[gr] = pd; }
    }
}

// GAT2: h2 = relu(t1 + b1) @ W2; fused dots (half-warp reduce). 256 thr.
__global__ __launch_bounds__(256) void k_gemm2(
        const float* __restrict__ W2, const float* __restrict__ b1,
        const float* __restrict__ as2, const float* __restrict__ ad2, int n) {
    extern __shared__ float smem[];
    float* sA = smem;
    float* sW = smem + 128 * 68;      // 2048
    int tid = threadIdx.x;
    for (int i = tid; i < 2048; i += 256) sW[i] = W2[i];
    int rbase = blockIdx.x * 128;
#pragma unroll
    for (int it = 0; it < 8; it++) {
        int idx = it * 256 + tid, row = idx >> 4, k4 = idx & 15;
        int gr = rbase + row;
        float4 v = make_float4(0.f, 0.f, 0.f, 0.f);
        if (gr < n) {
            float4 a = ((const float4*)g_acc)[(size_t)gr * 16 + k4];
            float4 b = __ldg((const float4*)b1 + k4);
            v = make_float4(fmaxf(a.x + b.x, 0.f), fmaxf(a.y + b.y, 0.f),
                            fmaxf(a.z + b.z, 0.f), fmaxf(a.w + b.w, 0.f));
        }
        *(float4*)&sA[row * 68 + k4 * 4] = v;
    }
    __syncthreads();
    int ci = tid & 15, ri = tid >> 4;
    ull acc[8];
#pragma unroll
    for (int i = 0; i < 8; i++) acc[i] = 0ull;
    gemm_core2<16>(sA, sW, acc, ri, ci);
    float2 asv = __ldg((const float2*)as2 + ci);
    float2 adv = __ldg((const float2*)ad2 + ci);
#pragma unroll
    for (int j = 0; j < 8; j++) {
        int gr = rbase + ri * 8 + j;
        float2 p = upk(acc[j]);
        if (gr < n) ((float2*)g_h2)[(size_t)gr * 16 + ci] = p;
        float ps = p.x * asv.x + p.y * asv.y;
        float pd = p.x * adv.x + p.y * adv.y;
#pragma unroll
        for (int o = 8; o; o >>= 1) {
            ps += __shfl_xor_sync(0xFFFFFFFFu, ps, o);
            pd += __shfl_xor_sync(0xFFFFFFFFu, pd, o);
        }
        if (ci == 0 && gr < n) { g_ssrc[gr] = ps; g_sdst[gr] = pd; }
    }
}

// ---------------- GAT aggregation: split-state online softmax over CSR --------
// Two independent (m, den, acc) states; edges alternate between them; merged at
// the end (grouped summation — numerically identical softmax). Doubles MLP and
// halves the dependent rescale chain.
template<int L, bool FINAL>
__global__ void k_gat_agg(float4* __restrict__ out_arg,
                          const float4* __restrict__ bias, int n) {
    const float4* h4 = (L == 16) ? (const float4*)g_h1 : (const float4*)g_h2;
    float4* out4 = FINAL ? out_arg : (float4*)g_acc;
    int t = blockIdx.x * blockDim.x + threadIdx.x;
    int g = t / L, q = t % L;
    if (g >= n) return;
    unsigned o = g_off[g], c = g_cnt[g];
    float sdp = g_sdst[g];
    // state 0 seeded with self-loop
    float m0 = lrelu(g_ssrc[g] + sdp);
    float4 a0 = h4[(size_t)g * L + q];
    float d0 = 1.f;
    // state 1 empty
    float m1 = -3.0e38f;
    float4 a1 = make_float4(0.f, 0.f, 0.f, 0.f);
    float d1 = 0.f;
    unsigned j = 0;
    for (; j + 2 <= c; j += 2) {
        int s0 = __ldg(&g_csr[o + j]);
        int s1 = __ldg(&g_csr[o + j + 1]);
        float ss0 = g_ssrc[s0];
        float ss1 = g_ssrc[s1];
        float4 v0 = h4[(size_t)s0 * L + q];
        float4 v1 = h4[(size_t)s1 * L + q];
        float l0 = lrelu(ss0 + sdp);
        float l1 = lrelu(ss1 + sdp);
        float w0;
        if (l0 > m0) {
            float r = __expf(m0 - l0);
            a0.x *= r; a0.y *= r; a0.z *= r; a0.w *= r;
            d0 *= r; m0 = l0; w0 = 1.f;
        } else w0 = __expf(l0 - m0);
        a0.x = fmaf(w0, v0.x, a0.x); a0.y = fmaf(w0, v0.y, a0.y);
        a0.z = fmaf(w0, v0.z, a0.z); a0.w = fmaf(w0, v0.w, a0.w);
        d0 += w0;
        float w1;
        if (l1 > m1) {
            float r = __expf(m1 - l1);
            a1.x *= r; a1.y *= r; a1.z *= r; a1.w *= r;
            d1 *= r; m1 = l1; w1 = 1.f;
        } else w1 = __expf(l1 - m1);
        a1.x = fmaf(w1, v1.x, a1.x); a1.y = fmaf(w1, v1.y, a1.y);
        a1.z = fmaf(w1, v1.z, a1.z); a1.w = fmaf(w1, v1.w, a1.w);
        d1 += w1;
    }
    if (j < c) {
        int s0 = __ldg(&g_csr[o + j]);
        float ss0 = g_ssrc[s0];
        float4 v0 = h4[(size_t)s0 * L + q];
        float l0 = lrelu(ss0 + sdp);
        float w0;
        if (l0 > m0) {
            float r = __expf(m0 - l0);
            a0.x *= r; a0.y *= r; a0.z *= r; a0.w *= r;
            d0 *= r; m0 = l0; w0 = 1.f;
        } else w0 = __expf(l0 - m0);
        a0.x = fmaf(w0, v0.x, a0.x); a0.y = fmaf(w0, v0.y, a0.y);
        a0.z = fmaf(w0, v0.z, a0.z); a0.w = fmaf(w0, v0.w, a0.w);
        d0 += w0;
    }
    // merge states (m0 is always finite; m1 may be -inf-like -> r=0)
    float4 acc; float den;
    if (m0 >= m1) {
        float r = __expf(m1 - m0);
        acc = make_float4(fmaf(r, a1.x, a0.x), fmaf(r, a1.y, a0.y),
                          fmaf(r, a1.z, a0.z), fmaf(r, a1.w, a0.w));
        den = fmaf(r, d1, d0);
    } else {
        float r = __expf(m0 - m1);
        acc = make_float4(fmaf(r, a0.x, a1.x), fmaf(r, a0.y, a1.y),
                          fmaf(r, a0.z, a1.z), fmaf(r, a0.w, a1.w));
        den = fmaf(r, d0, d1);
    }
    float rd = 1.f / den;
    float4 r4 = make_float4(acc.x * rd, acc.y * rd, acc.z * rd, acc.w * rd);
    if (FINAL) {
        float4 b = __ldg(bias + q);
        r4.x += b.x; r4.y += b.y; r4.z += b.z; r4.w += b.w;
    }
    out4[(size_t)g * L + q] = r4;
}

// ---------------- launch ------------------------------------------------------
extern "C" void kernel_launch(void* const* d_in, const int* in_sizes, int n_in,
                              void* d_out, int out_size) {
    const float* x    = (const float*)d_in[0];
    const int*   ei   = (const int*)  d_in[1];
    const float* Wout = (const float*)d_in[2];
    const float* bout = (const float*)d_in[3];
    const float* Wroot= (const float*)d_in[4];
    const float* W1   = (const float*)d_in[5];
    const float* as1  = (const float*)d_in[6];
    const float* ad1  = (const float*)d_in[7];
    const float* b1   = (const float*)d_in[8];
    const float* W2   = (const float*)d_in[9];
    const float* as2  = (const float*)d_in[10];
    const float* ad2  = (const float*)d_in[11];
    const float* b2   = (const float*)d_in[12];

    int n = in_sizes[0] / 64;
    int e = in_sizes[1] / 2;
    const int* src = ei;
    const int* dst = ei + e;

    // Deterministic, idempotent, capture-safe: opt in to >48KB dynamic smem.
    cudaFuncSetAttribute(k_gemm0, cudaFuncAttributeMaxDynamicSharedMemorySize, 128*68*4 + 32768);
    cudaFuncSetAttribute(k_gemm1, cudaFuncAttributeMaxDynamicSharedMemorySize, 128*68*4 + 16384);

    const int TB = 256;
    int nbs   = (n + 255) / 256;
    int nb_e  = (e + TB - 1) / TB;
    int nb_g  = (n + 127) / 128;
    int nb_16 = (n * 16 + TB - 1) / TB;
    int nb_8  = (n * 8 + TB - 1) / TB;

    // CSR build
    k_zero_cnt<<<nbs, TB>>>(n);
    k_hist    <<<nb_e, TB>>>(dst, e);
    k_scanA   <<<nbs, 256>>>(n);
    k_scanB   <<<1, 512>>>(nbs);
    k_scanC   <<<nbs, 256>>>(n);
    k_scatter <<<nb_e, TB>>>(src, dst, e);

    // Layer 0: ClusterGCN
    k_agg0 <<<nb_16, TB>>>((const float4*)x, n);
    k_gemm0<<<nb_g, 512, 128*68*4 + 32768>>>((const float4*)x, Wout, bout, Wroot, n);

    // Layer 1: GAT(64->64)  (dots fused into gemm1 epilogue)
    k_gemm1<<<nb_g, 512, 128*68*4 + 16384>>>(W1, as1, ad1, n);
    k_gat_agg<16, false><<<nb_16, TB>>>(nullptr, nullptr, n);

    // Layer 2: GAT(64->32)  (dots fused into gemm2 epilogue)
    k_gemm2<<<nb_g, 256, 128*68*4 + 8192>>>(W2, b1, as2, ad2, n);
    k_gat_agg<8, true><<<nb_8, TB>>>((float4*)d_out, (const float4*)b2, n);
}